// round 12
// baseline (speedup 1.0000x reference)
#include <cuda_runtime.h>
#include <cuda_bf16.h>
#include <math.h>

#define ENT 250000
#define RELN 64
#define D 128
#define BB 32768
#define KK 8
#define NNEG (BB*KK)

#define NBLK 512           // persistent grid (co-resident: <= 148 SMs * 4 blocks)
#define TILES 4096         // tile = 8 batch elements (8 pos rows, 64 neg rows)
#define SLOTS 8            // TILES / NBLK, uniform

typedef unsigned long long u64;

// Scratch (device globals; ticket/flag are MONOTONIC across launches/replays)
__device__ int g_hist_pos[TILES*4];
__device__ int g_hist_neg[TILES*4];
__device__ int g_off_pos[TILES*4];
__device__ int g_off_neg[TILES*4];
__device__ u64 g_ticket;
__device__ u64 g_flag;

__device__ __forceinline__ u64 ld_acq(const u64* p) {
    u64 v;
    asm volatile("ld.global.acquire.gpu.u64 %0, [%1];" : "=l"(v) : "l"(p) : "memory");
    return v;
}

__device__ __forceinline__ float warpsum(float v) {
    v += __shfl_xor_sync(0xFFFFFFFFu, v, 16);
    v += __shfl_xor_sync(0xFFFFFFFFu, v, 8);
    v += __shfl_xor_sync(0xFFFFFFFFu, v, 4);
    v += __shfl_xor_sync(0xFFFFFFFFu, v, 2);
    v += __shfl_xor_sync(0xFFFFFFFFu, v, 1);
    return v;
}

__device__ __forceinline__ float4 ld4(const float* base, int lane) {
    return reinterpret_cast<const float4*>(base)[lane];
}

// TransH projection: e - (e.n) n with n = m / max(||m||, 1e-12)
__device__ __forceinline__ float4 map4(float4 e, float4 m) {
    float mm = m.x*m.x + m.y*m.y + m.z*m.z + m.w*m.w;
    float em = e.x*m.x + e.y*m.y + e.z*m.z + e.w*m.w;
    mm = warpsum(mm);
    em = warpsum(em);
    float dn = fmaxf(sqrtf(mm), 1e-12f);
    float coef = em / (dn*dn);
    float4 r;
    r.x = e.x - coef*m.x;
    r.y = e.y - coef*m.y;
    r.z = e.z - coef*m.z;
    r.w = e.w - coef*m.w;
    return r;
}

__device__ __forceinline__ float dot4w(float4 a, float4 b) {
    return warpsum(a.x*b.x + a.y*b.y + a.z*b.z + a.w*b.w);
}

// Scan one 4096-entry x 4-class histogram array -> global offsets with class
// bases.  Run by the scanner block only, all 256 threads, 16 entries/thread.
// Classes packed 2-per-u64 (32-bit lanes).
__device__ void scan4096(const int* __restrict__ hist, int* __restrict__ off,
                         int t, u64* sA, u64* sB, u64* sTot)
{
    int lane = t & 31, w = t >> 5;
    const int E = TILES / 256;    // 16
    int e0 = t * E;

    u64 a = 0, b = 0;
    #pragma unroll 4
    for (int e = 0; e < E; e++) {
        int4 h = *reinterpret_cast<const int4*>(hist + (e0 + e) * 4);
        a += (u64)(unsigned)h.x | ((u64)(unsigned)h.y << 32);
        b += (u64)(unsigned)h.z | ((u64)(unsigned)h.w << 32);
    }
    u64 A = a, B = b;
    #pragma unroll
    for (int d = 1; d < 32; d <<= 1) {
        u64 ua = __shfl_up_sync(0xFFFFFFFFu, A, d);
        u64 ub = __shfl_up_sync(0xFFFFFFFFu, B, d);
        if (lane >= d) { A += ua; B += ub; }
    }
    if (lane == 31) { sA[w] = A; sB[w] = B; }
    __syncthreads();
    if (t == 0) {
        u64 xa = 0, xb = 0;
        #pragma unroll
        for (int i2 = 0; i2 < 8; i2++) {
            u64 ta = sA[i2], tb = sB[i2];
            sA[i2] = xa; sB[i2] = xb;
            xa += ta; xb += tb;
        }
        sTot[0] = xa; sTot[1] = xb;
    }
    __syncthreads();
    u64 exA = A - a + sA[w];
    u64 exB = B - b + sB[w];
    u64 totA = sTot[0], totB = sTot[1];
    int base0 = 0;
    int base1 = base0 + (int)(unsigned)totA;
    int base2 = base1 + (int)(unsigned)(totA >> 32);
    int base3 = base2 + (int)(unsigned)totB;
    u64 pA = exA, pB = exB;
    for (int e = 0; e < E; e++) {
        int4 h = *reinterpret_cast<const int4*>(hist + (e0 + e) * 4);
        int4 o;
        o.x = base0 + (int)(unsigned)pA;
        o.y = base1 + (int)(unsigned)(pA >> 32);
        o.z = base2 + (int)(unsigned)pB;
        o.w = base3 + (int)(unsigned)(pB >> 32);
        *reinterpret_cast<int4*>(off + (e0 + e) * 4) = o;
        pA += (u64)(unsigned)h.x | ((u64)(unsigned)h.y << 32);
        pB += (u64)(unsigned)h.z | ((u64)(unsigned)h.w << 32);
    }
}

__global__ void __launch_bounds__(256, 4) k_fused(
    const float* __restrict__ ie, const float* __restrict__ oe,
    const float* __restrict__ ir, const float* __restrict__ orr,
    const float* __restrict__ im, const float* __restrict__ om,
    const int* __restrict__ inl, const int* __restrict__ pl, const int* __restrict__ nl,
    float* __restrict__ out)
{
    __shared__ unsigned char s_ncls[64];
    __shared__ unsigned char s_pcls[8];
    __shared__ float          s_nloss[SLOTS][64];
    __shared__ unsigned short s_ncode[SLOTS][64];   // (class<<8)|rank, rank<64
    __shared__ float          s_ploss[SLOTS][8];
    __shared__ unsigned short s_pcode[SLOTS][8];    // (class<<8)|rank, rank<8
    __shared__ u64 s_epoch;
    __shared__ int s_scanner;
    __shared__ u64 s_sA[8], s_sB[8], s_sTot[2];

    int t = threadIdx.x, lane = t & 31, w = t >> 5;

    // ======================= tile loop (8 tiles/block) ======================
    #pragma unroll 1
    for (int s = 0; s < SLOTS; s++) {
        int tile = blockIdx.x + s*NBLK;
        int i = tile*8 + w;                 // batch element for this warp

        __syncthreads();                    // guard s_ncls/s_pcls reuse

        int ilab = __ldg(inl + i);
        int plab = __ldg(pl + i);
        int nlab_l = (lane < KK) ? __ldg(nl + i*KK + lane) : 0;

        if (lane == 0) out[i] = 0.0f;       // fused output zeroing

        bool ei = ilab < ENT;
        int iid   = ei ? ilab : (ilab - ENT);
        int iid_r = min(iid, RELN - 1);
        const float* ain = ei ? (ie + (long)iid*D) : (ir + iid_r*D);
        const float* aom = om + iid_r*D;    // rare out-side projection row

        bool ep = plab < ENT;
        int pid   = ep ? plab : (plab - ENT);
        int pid_r = min(pid, RELN - 1);
        const float* apos = ep ? (oe + (long)pid*D) : (orr + pid_r*D);

        bool en[KK];
        int nid_r[KK];
        const float* aneg[KK];
        #pragma unroll
        for (int r = 0; r < KK; r++) {
            int nlab = __shfl_sync(0xFFFFFFFFu, nlab_l, r);
            en[r] = nlab < ENT;
            int nid = en[r] ? nlab : (nlab - ENT);
            nid_r[r] = min(nid, RELN - 1);
            aneg[r] = en[r] ? (oe + (long)nid*D) : (orr + nid_r[r]*D);
        }

        // issue all 10 independent row gathers (prep below overlaps latency)
        float4 vin  = ld4(ain, lane);
        float4 vpos = ld4(apos, lane);
        float4 vneg[KK];
        #pragma unroll
        for (int r = 0; r < KK; r++) vneg[r] = ld4(aneg[r], lane);

        // ---------------- prep: classes + stable ranks + histogram ----------
        int cpos = (ei ? 0 : 2) + (ep ? 0 : 1);
        bool en_self = nlab_l < ENT;                       // valid for lane<8
        int cneg = (ei ? 0 : 2) + (en_self ? 0 : 1);
        if (lane < KK) s_ncls[w*KK + lane] = (unsigned char)cneg;
        if (lane == 8) s_pcls[w] = (unsigned char)cpos;
        __syncthreads();

        int nrank = 0;
        if (lane < KK) {
            int idx = w*KK + lane;
            for (int j = 0; j < idx; j++) nrank += (s_ncls[j] == cneg);
        }
        int prank = 0;
        if (lane == 8) {
            for (int j = 0; j < w; j++) prank += (s_pcls[j] == cpos);
        }
        if (w == 0 && lane < 4) {
            int cnt = 0;
            for (int j = 0; j < 64; j++) cnt += (s_ncls[j] == lane);
            g_hist_neg[tile*4 + lane] = cnt;
        }
        if (w == 1 && lane < 4) {
            int cnt = 0;
            for (int j = 0; j < 8; j++) cnt += (s_pcls[j] == lane);
            g_hist_pos[tile*4 + lane] = cnt;
        }
        if (lane < KK)  s_ncode[s][w*KK + lane] = (unsigned short)((cneg << 8) | nrank);
        if (lane == 8)  s_pcode[s][w] = (unsigned short)((cpos << 8) | prank);

        // ---------------- dots (rare warp-uniform projection fixups) --------
        float4 vin_pos = vin;
        if (ei && !ep) vin_pos = map4(vin, ld4(im + pid_r*D, lane));
        float4 vout_pos = vpos;
        if (ep && !ei) vout_pos = map4(vpos, ld4(aom, lane));
        float dpos = dot4w(vin_pos, vout_pos);

        float dneg[KK];
        #pragma unroll
        for (int r = 0; r < KK; r++) {
            float4 vi = vin;
            if (ei && !en[r]) vi = map4(vin, ld4(im + nid_r[r]*D, lane));
            float4 vo = vneg[r];
            if (en[r] && !ei) vo = map4(vneg[r], ld4(aom, lane));
            dneg[r] = dot4w(vi, vo);
        }

        // losses (store NEGATED log-sigmoid, ready to accumulate)
        if (lane < KK) {
            float dd = dneg[0];
            #pragma unroll
            for (int q = 1; q < KK; q++) if (lane == q) dd = dneg[q];
            float x = -dd;
            float ls = fminf(x, 0.0f) - log1pf(expf(-fabsf(x)));
            s_nloss[s][w*KK + lane] = -ls;
        }
        if (lane == 8) {
            float x = dpos;
            float ls = fminf(x, 0.0f) - log1pf(expf(-fabsf(x)));
            s_ploss[s][w] = -ls;
        }
    }

    // ======================= global barrier via ticket ======================
    __syncthreads();
    if (t == 0) {
        __threadfence();                                   // release hist + zeroes
        u64 tkt = atomicAdd(&g_ticket, 1ULL);
        s_epoch = tkt / NBLK;
        s_scanner = ((tkt % NBLK) == (NBLK - 1)) ? 1 : 0;
    }
    __syncthreads();

    if (s_scanner) {
        __threadfence();                                   // acquire all hists
        scan4096(g_hist_neg, g_off_neg, t, s_sA, s_sB, s_sTot);
        __syncthreads();
        scan4096(g_hist_pos, g_off_pos, t, s_sA, s_sB, s_sTot);
        __syncthreads();
        if (t == 0) {
            __threadfence();                               // release offsets
            atomicAdd(&g_flag, 1ULL);
        }
    }

    if (t == 0) {
        u64 target = s_epoch + 1;
        while (ld_acq(&g_flag) < target) __nanosleep(64);
    }
    __syncthreads();
    __threadfence();

    // ======================= scatter with permutation =======================
    #pragma unroll 1
    for (int s = 0; s < SLOTS; s++) {
        int tile = blockIdx.x + s*NBLK;
        if (lane < KK) {
            unsigned code = s_ncode[s][w*KK + lane];
            int c = code >> 8, rk = code & 0xFF;
            int pos = g_off_neg[tile*4 + c] + rk;          // sorted neg position
            atomicAdd(&out[pos >> 3], s_nloss[s][w*KK + lane]);
        }
        if (lane == 8) {
            unsigned code = s_pcode[s][w];
            int c = code >> 8, rk = code & 0xFF;
            int pos = g_off_pos[tile*4 + c] + rk;
            atomicAdd(&out[pos], s_ploss[s][w]);
        }
    }
}

extern "C" void kernel_launch(void* const* d_in, const int* in_sizes, int n_in,
                              void* d_out, int out_size)
{
    const float* ie  = (const float*)d_in[0];  // in_ent_w
    const float* oe  = (const float*)d_in[1];  // out_ent_w
    const float* ir  = (const float*)d_in[2];  // in_rel_w
    const float* orr = (const float*)d_in[3];  // out_rel_w
    const float* im  = (const float*)d_in[4];  // in_map_w
    const float* om  = (const float*)d_in[5];  // out_map_w
    const int* inl = (const int*)d_in[6];      // input_labels
    const int* pl  = (const int*)d_in[7];      // pos_labels
    const int* nl  = (const int*)d_in[8];      // neg_labels (B*K)
    float* out = (float*)d_out;

    k_fused<<<NBLK, 256>>>(ie, oe, ir, orr, im, om, inl, pl, nl, out);
}

// round 13
// speedup vs baseline: 1.7463x; 1.7463x over previous
#include <cuda_runtime.h>
#include <cuda_bf16.h>
#include <math.h>

#define ENT 250000
#define RELN 64
#define D 128
#define BB 32768
#define KK 8
#define NNEG (BB*KK)

#define ROWS_PER_BLK 1024
#define HBLK_POS (BB/ROWS_PER_BLK)    // 32
#define HBLK_NEG (NNEG/ROWS_PER_BLK)  // 256
#define NBLK_DOT (BB/8)               // 4096 blocks in k_dot

typedef unsigned long long u64;

// Scratch (device globals). g_ticket/g_flag are MONOTONIC across replays.
__device__ unsigned short g_cr_pos[BB];    // (class<<12) | local_rank
__device__ unsigned short g_cr_neg[NNEG];
__device__ int g_hist_pos[HBLK_POS*4];
__device__ int g_hist_neg[HBLK_NEG*4];
__device__ int g_off_pos[HBLK_POS*4];
__device__ int g_off_neg[HBLK_NEG*4];
__device__ u64 g_ticket;
__device__ u64 g_flag;

__device__ __forceinline__ u64 ld_acq(const u64* p) {
    u64 v;
    asm volatile("ld.global.acquire.gpu.u64 %0, [%1];" : "=l"(v) : "l"(p) : "memory");
    return v;
}

// ---------------------------------------------------------------------------
// K1: branch classification + per-block stable rank + per-block histogram.
// 256 threads/block, 4 rows/thread (1024 rows/block).
// Blocks [0, HBLK_POS) = pos rows (also zero `out`); rest = neg rows.
// (identical to the benched 39.6us version)
// ---------------------------------------------------------------------------
__global__ void __launch_bounds__(256) k_prep(
    const int* __restrict__ inl, const int* __restrict__ pl,
    const int* __restrict__ nl, float* __restrict__ out)
{
    int blk = blockIdx.x;
    bool is_pos = (blk < HBLK_POS);
    int t = threadIdx.x;
    int lane = t & 31, warp = t >> 5;

    int rowbase;
    int c[4];
    if (is_pos) {
        rowbase = blk*ROWS_PER_BLK + t*4;
        int4 il  = *reinterpret_cast<const int4*>(inl + rowbase);
        int4 plv = *reinterpret_cast<const int4*>(pl + rowbase);
        *reinterpret_cast<float4*>(out + rowbase) = make_float4(0.f,0.f,0.f,0.f);
        c[0] = ((il.x >= ENT) ? 2 : 0) + ((plv.x >= ENT) ? 1 : 0);
        c[1] = ((il.y >= ENT) ? 2 : 0) + ((plv.y >= ENT) ? 1 : 0);
        c[2] = ((il.z >= ENT) ? 2 : 0) + ((plv.z >= ENT) ? 1 : 0);
        c[3] = ((il.w >= ENT) ? 2 : 0) + ((plv.w >= ENT) ? 1 : 0);
    } else {
        rowbase = (blk - HBLK_POS)*ROWS_PER_BLK + t*4;
        int ilv = inl[rowbase >> 3];               // constant across the 4 rows
        int4 nlv = *reinterpret_cast<const int4*>(nl + rowbase);
        int ci = (ilv >= ENT) ? 2 : 0;
        c[0] = ci + ((nlv.x >= ENT) ? 1 : 0);
        c[1] = ci + ((nlv.y >= ENT) ? 1 : 0);
        c[2] = ci + ((nlv.z >= ENT) ? 1 : 0);
        c[3] = ci + ((nlv.w >= ENT) ? 1 : 0);
    }

    u64 cnt = 0;
    #pragma unroll
    for (int j = 0; j < 4; j++) cnt += 1ULL << (16*c[j]);

    u64 s = cnt;
    #pragma unroll
    for (int d = 1; d < 32; d <<= 1) {
        u64 u = __shfl_up_sync(0xFFFFFFFFu, s, d);
        if (lane >= d) s += u;
    }
    u64 wexcl = s - cnt;

    __shared__ u64 wtot[8];
    __shared__ u64 wbase[8];
    __shared__ u64 btot;
    if (lane == 31) wtot[warp] = s;
    __syncthreads();
    if (t == 0) {
        u64 a = 0;
        #pragma unroll
        for (int i = 0; i < 8; i++) { u64 tv = wtot[i]; wbase[i] = a; a += tv; }
        btot = a;
    }
    __syncthreads();

    u64 excl = wexcl + wbase[warp];

    u64 outpk = 0;
    #pragma unroll
    for (int j = 0; j < 4; j++) {
        int cc = c[j];
        int rk = (int)((excl >> (16*cc)) & 0xFFFFULL);
        excl += 1ULL << (16*cc);
        outpk |= ((u64)((cc << 12) | rk)) << (16*j);
    }

    if (is_pos) {
        *reinterpret_cast<u64*>(g_cr_pos + rowbase) = outpk;
        if (t < 4) g_hist_pos[blk*4 + t] = (int)((btot >> (16*t)) & 0xFFFFULL);
    } else {
        *reinterpret_cast<u64*>(g_cr_neg + rowbase) = outpk;
        if (t < 4) g_hist_neg[(blk - HBLK_POS)*4 + t] = (int)((btot >> (16*t)) & 0xFFFFULL);
    }
}

// ---------------------------------------------------------------------------
// Histogram scan (both sets), run by block 0 of k_dot with 256 threads.
// Identical math to the benched k_scan2.
// ---------------------------------------------------------------------------
__device__ void do_scan(int t)
{
    int lane = t & 31, w = t >> 5;
    __shared__ u64 sA[8], sB[8];
    __shared__ u64 gTotA, gTotB;

    // ---- neg (256 entries) ----
    unsigned h0 = g_hist_neg[t*4+0], h1 = g_hist_neg[t*4+1];
    unsigned h2 = g_hist_neg[t*4+2], h3 = g_hist_neg[t*4+3];
    u64 ownA = (u64)h0 | ((u64)h1 << 32);
    u64 ownB = (u64)h2 | ((u64)h3 << 32);
    u64 A = ownA, B = ownB;
    #pragma unroll
    for (int d = 1; d < 32; d <<= 1) {
        u64 ua = __shfl_up_sync(0xFFFFFFFFu, A, d);
        u64 ub = __shfl_up_sync(0xFFFFFFFFu, B, d);
        if (lane >= d) { A += ua; B += ub; }
    }
    if (lane == 31) { sA[w] = A; sB[w] = B; }
    __syncthreads();
    if (t == 0) {
        u64 a = 0, b = 0;
        #pragma unroll
        for (int i = 0; i < 8; i++) {
            u64 ta = sA[i], tb = sB[i];
            sA[i] = a; sB[i] = b;
            a += ta; b += tb;
        }
        gTotA = a; gTotB = b;
    }
    __syncthreads();
    u64 excA = A + sA[w] - ownA;
    u64 excB = B + sB[w] - ownB;
    {
        unsigned n0 = (unsigned)(gTotA), n1 = (unsigned)(gTotA >> 32);
        unsigned n2 = (unsigned)(gTotB);
        int base0 = 0;
        int base1 = base0 + (int)n0;
        int base2 = base1 + (int)n1;
        int base3 = base2 + (int)n2;
        g_off_neg[t*4+0] = base0 + (int)(excA & 0xFFFFFFFFULL);
        g_off_neg[t*4+1] = base1 + (int)(excA >> 32);
        g_off_neg[t*4+2] = base2 + (int)(excB & 0xFFFFFFFFULL);
        g_off_neg[t*4+3] = base3 + (int)(excB >> 32);
    }

    // ---- pos (32 entries), warp 0 only ----
    if (w == 0) {
        unsigned p0 = g_hist_pos[lane*4+0], p1 = g_hist_pos[lane*4+1];
        unsigned p2 = g_hist_pos[lane*4+2], p3 = g_hist_pos[lane*4+3];
        u64 oA = (u64)p0 | ((u64)p1 << 32);
        u64 oB = (u64)p2 | ((u64)p3 << 32);
        u64 PA = oA, PB = oB;
        #pragma unroll
        for (int d = 1; d < 32; d <<= 1) {
            u64 ua = __shfl_up_sync(0xFFFFFFFFu, PA, d);
            u64 ub = __shfl_up_sync(0xFFFFFFFFu, PB, d);
            if (lane >= d) { PA += ua; PB += ub; }
        }
        u64 tA = __shfl_sync(0xFFFFFFFFu, PA, 31);
        u64 tB = __shfl_sync(0xFFFFFFFFu, PB, 31);
        u64 eA = PA - oA, eB = PB - oB;
        unsigned q0 = (unsigned)tA, q1 = (unsigned)(tA >> 32), q2 = (unsigned)tB;
        int base0 = 0;
        int base1 = base0 + (int)q0;
        int base2 = base1 + (int)q1;
        int base3 = base2 + (int)q2;
        g_off_pos[lane*4+0] = base0 + (int)(eA & 0xFFFFFFFFULL);
        g_off_pos[lane*4+1] = base1 + (int)(eA >> 32);
        g_off_pos[lane*4+2] = base2 + (int)(eB & 0xFFFFFFFFULL);
        g_off_pos[lane*4+3] = base3 + (int)(eB >> 32);
    }
}

// ---------------------------------------------------------------------------
// K2: dot kernel — one warp per batch element (benched structure) + block 0
// runs the scan up front; all blocks spin on the epoch flag ONLY right
// before their epilogue scatter.
// ---------------------------------------------------------------------------
__device__ __forceinline__ float warpsum(float v) {
    v += __shfl_xor_sync(0xFFFFFFFFu, v, 16);
    v += __shfl_xor_sync(0xFFFFFFFFu, v, 8);
    v += __shfl_xor_sync(0xFFFFFFFFu, v, 4);
    v += __shfl_xor_sync(0xFFFFFFFFu, v, 2);
    v += __shfl_xor_sync(0xFFFFFFFFu, v, 1);
    return v;
}

__device__ __forceinline__ float4 ld4(const float* base, int lane) {
    return reinterpret_cast<const float4*>(base)[lane];
}

__device__ __forceinline__ float4 map4(float4 e, float4 m) {
    float mm = m.x*m.x + m.y*m.y + m.z*m.z + m.w*m.w;
    float em = e.x*m.x + e.y*m.y + e.z*m.z + e.w*m.w;
    mm = warpsum(mm);
    em = warpsum(em);
    float dn = fmaxf(sqrtf(mm), 1e-12f);
    float coef = em / (dn*dn);
    float4 r;
    r.x = e.x - coef*m.x;
    r.y = e.y - coef*m.y;
    r.z = e.z - coef*m.z;
    r.w = e.w - coef*m.w;
    return r;
}

__device__ __forceinline__ float dot4w(float4 a, float4 b) {
    return warpsum(a.x*b.x + a.y*b.y + a.z*b.z + a.w*b.w);
}

__global__ void __launch_bounds__(256) k_dot(
    const float* __restrict__ ie, const float* __restrict__ oe,
    const float* __restrict__ ir, const float* __restrict__ orr,
    const float* __restrict__ im, const float* __restrict__ om,
    const int* __restrict__ inl, const int* __restrict__ pl, const int* __restrict__ nl,
    float* __restrict__ out)
{
    __shared__ u64 s_epoch;
    int t = threadIdx.x;
    int lane = t & 31;

    // take an epoch ticket (replay-safe: 4096 tickets per launch instance)
    if (t == 0) {
        u64 tkt = atomicAdd(&g_ticket, 1ULL);
        s_epoch = tkt / (u64)NBLK_DOT;
    }

    // block 0: scan histograms -> offsets, publish flag (hidden under other
    // blocks' gathers; block 0 is in wave 1)
    if (blockIdx.x == 0) {
        do_scan(t);
        __syncthreads();
        if (t == 0) {
            __threadfence();
            atomicAdd(&g_flag, 1ULL);
        }
    }

    int i = blockIdx.x*8 + (t >> 5);       // batch element for this warp

    int ilab = __ldg(inl + i);
    int plab = __ldg(pl + i);
    int nlab_l = (lane < KK) ? __ldg(nl + i*KK + lane) : 0;

    bool ei = ilab < ENT;
    int iid  = ei ? ilab : (ilab - ENT);
    int iid_r = min(iid, RELN - 1);
    const float* ain = ei ? (ie + (long)iid*D) : (ir + iid_r*D);
    const float* aom = om + iid_r*D;       // rare out-side projection row

    bool ep = plab < ENT;
    int pid  = ep ? plab : (plab - ENT);
    int pid_r = min(pid, RELN - 1);
    const float* apos = ep ? (oe + (long)pid*D) : (orr + pid_r*D);

    bool en[KK];
    int nid_r[KK];
    const float* aneg[KK];
    #pragma unroll
    for (int r = 0; r < KK; r++) {
        int nlab = __shfl_sync(0xFFFFFFFFu, nlab_l, r);
        en[r] = nlab < ENT;
        int nid = en[r] ? nlab : (nlab - ENT);
        nid_r[r] = min(nid, RELN - 1);
        aneg[r] = en[r] ? (oe + (long)nid*D) : (orr + nid_r[r]*D);
    }

    // issue all 10 independent row gathers back-to-back (MLP=10)
    float4 vin  = ld4(ain, lane);
    float4 vpos = ld4(apos, lane);
    float4 vneg[KK];
    #pragma unroll
    for (int r = 0; r < KK; r++) vneg[r] = ld4(aneg[r], lane);

    // ---- pos pair (rare warp-uniform projection fixups) ----
    float4 vin_pos = vin;
    if (ei && !ep) vin_pos = map4(vin, ld4(im + pid_r*D, lane));
    float4 vout_pos = vpos;
    if (ep && !ei) vout_pos = map4(vpos, ld4(aom, lane));
    float dpos = dot4w(vin_pos, vout_pos);

    // ---- neg pairs ----
    float dneg[KK];
    #pragma unroll
    for (int r = 0; r < KK; r++) {
        float4 vi = vin;
        if (ei && !en[r]) vi = map4(vin, ld4(im + nid_r[r]*D, lane));
        float4 vo = vneg[r];
        if (en[r] && !ei) vo = map4(vneg[r], ld4(aom, lane));
        dneg[r] = dot4w(vi, vo);
    }

    // wait for offsets (block 0 published them ~1-2us into the kernel; for
    // nearly all blocks this spin is already satisfied)
    __syncthreads();                        // also makes s_epoch visible
    if (t == 0) {
        u64 target = s_epoch + 1;
        while (ld_acq(&g_flag) < target) __nanosleep(32);
    }
    __syncthreads();
    __threadfence();

    // ---- epilogue: lane 0 = pos row, lanes 1..8 = neg rows ----
    if (lane <= KK) {
        float x;
        int tgt;
        if (lane == 0) {
            x = dpos;
            unsigned v = g_cr_pos[i];
            tgt = g_off_pos[(i >> 10)*4 + (v >> 12)] + (v & 0xFFF);
        } else {
            int r = lane - 1;
            float dd = dneg[0];
            #pragma unroll
            for (int q = 1; q < KK; q++) if (r == q) dd = dneg[q];
            x = -dd;
            int j = i*KK + r;
            unsigned v = g_cr_neg[j];
            int s = g_off_neg[(j >> 10)*4 + (v >> 12)] + (v & 0xFFF);
            tgt = s >> 3;                  // reshape(b,k).sum(1)
        }
        float ls = fminf(x, 0.0f) - log1pf(expf(-fabsf(x)));
        atomicAdd(&out[tgt], -ls);
    }
}

extern "C" void kernel_launch(void* const* d_in, const int* in_sizes, int n_in,
                              void* d_out, int out_size)
{
    const float* ie  = (const float*)d_in[0];  // in_ent_w
    const float* oe  = (const float*)d_in[1];  // out_ent_w
    const float* ir  = (const float*)d_in[2];  // in_rel_w
    const float* orr = (const float*)d_in[3];  // out_rel_w
    const float* im  = (const float*)d_in[4];  // in_map_w
    const float* om  = (const float*)d_in[5];  // out_map_w
    const int* inl = (const int*)d_in[6];      // input_labels
    const int* pl  = (const int*)d_in[7];      // pos_labels
    const int* nl  = (const int*)d_in[8];      // neg_labels (B*K)
    float* out = (float*)d_out;

    k_prep<<<HBLK_POS + HBLK_NEG, 256>>>(inl, pl, nl, out);
    k_dot<<<NBLK_DOT, 256>>>(ie, oe, ir, orr, im, om, inl, pl, nl, out);
}